// round 8
// baseline (speedup 1.0000x reference)
#include <cuda_runtime.h>
#include <cuda_fp16.h>
#include <math.h>

namespace {
constexpr int KCODES = 1024;
constexpr int D      = 64;
constexpr int HWSZ   = 64 * 64;
constexpr int NTOK   = 32 * HWSZ;        // 131072
constexpr int TPB    = 256;              // 8 warps, 128 tokens/CTA
constexpr int TOKS   = 128;
constexpr int TILE   = 512;              // codes per smem tile (2 tiles)
constexpr float MARGIN = 0.08f;          // hard bound: f16 inputs + f16 accum (2-sided)
constexpr float RESCUE = 1e-4f;          // fp64 grid-rescue threshold (R2-proven)

constexpr int ASTRIDE_W = 36;            // A row stride in u32 words (144B)
constexpr int BSTRIDE_W = 36;
constexpr int SM_A  = 0;                 // 128 * 144B
constexpr int SM_B  = 18432;             // 512 * 144B
constexpr int SM_CN = 92160;             // 512 u32 (1024 f16 norms)
constexpr int SM_TOTAL = 94208;
constexpr int RGRID = 256;               // rescue grid
}

__device__ float    g_cnorm[KCODES];
__device__ __half   g_cn16[KCODES];
__device__ int      g_counts[KCODES];
__device__ unsigned g_cb16[KCODES * 32];   // f16x2 rows of (-2c)
__device__ int      g_nflag;
__device__ int      g_done;
__device__ int      g_ftok[NTOK];
__device__ uint4    g_fc0[NTOK];           // lanes 0-3: i0|(i1<<16)
__device__ uint4    g_fc1[NTOK];           // lanes 0-3: i2

__global__ void vq_nop() {}

// ---- Kernel A: warp-per-code prep (norms f32+f16, f16(-2c)) ----
__global__ void vq_prep(const float* __restrict__ codebook) {
    const int w    = (blockIdx.x * blockDim.x + threadIdx.x) >> 5;
    const int lane = threadIdx.x & 31;
    if (w >= KCODES) return;
    float a = codebook[w * D + 2 * lane];
    float b = codebook[w * D + 2 * lane + 1];
    __half2 h = __floats2half2_rn(-2.0f * a, -2.0f * b);
    g_cb16[w * 32 + lane] = *reinterpret_cast<unsigned*>(&h);
    float p = fmaf(a, a, b * b);
#pragma unroll
    for (int o = 16; o > 0; o >>= 1) p += __shfl_xor_sync(0xffffffffu, p, o);
    if (lane == 0) { g_cnorm[w] = p; g_cn16[w] = __float2half_rn(p); }
}

// Exact emulation of the reference's rounded score (proven in round 2).
__device__ __forceinline__ float ref_score(const float* __restrict__ cb, int k,
                                           const float* x, float A32) {
    const float* cp = cb + k * D;
    double dot = 0.0, C = 0.0;
#pragma unroll
    for (int i = 0; i < D; ++i) {
        float cv = cp[i];
        dot += (double)x[i] * (double)cv;
        C   += (double)(cv * cv);
    }
    float t1 = (float)dot;
    float t2 = A32 - 2.0f * t1;
    return t2 + (float)C;
}

__device__ __forceinline__ float fp32_score(const float* __restrict__ cb, int k,
                                            const float* x) {
    const float* cp = cb + k * D;
    float d0 = 0.f, d1 = 0.f, d2 = 0.f, d3 = 0.f;
#pragma unroll
    for (int i = 0; i < D / 4; ++i) {
        d0 = fmaf(x[4 * i + 0], __ldg(&cp[4 * i + 0]), d0);
        d1 = fmaf(x[4 * i + 1], __ldg(&cp[4 * i + 1]), d1);
        d2 = fmaf(x[4 * i + 2], __ldg(&cp[4 * i + 2]), d2);
        d3 = fmaf(x[4 * i + 3], __ldg(&cp[4 * i + 3]), d3);
    }
    return g_cnorm[k] - 2.0f * ((d0 + d1) + (d2 + d3));
}

__device__ __forceinline__ void ins2(float s, int i, float& b0, int& i0, float& b1, int& i1) {
    if (s < b0 || (s == b0 && i < i0)) { b1 = b0; i1 = i0; b0 = s; i0 = i; }
    else if (s < b1 || (s == b1 && i < i1)) { b1 = s; i1 = i; }
}
__device__ __forceinline__ void butterfly2(float& b0, int& i0, float& b1, int& i1) {
#pragma unroll
    for (int d = 1; d <= 2; d <<= 1) {
        float rb0 = __shfl_xor_sync(0xffffffffu, b0, d);
        float rb1 = __shfl_xor_sync(0xffffffffu, b1, d);
        int   ri0 = __shfl_xor_sync(0xffffffffu, i0, d);
        int   ri1 = __shfl_xor_sync(0xffffffffu, i1, d);
        ins2(rb0, ri0, b0, i0, b1, i1);
        ins2(rb1, ri1, b0, i0, b1, i1);
    }
}
// Strict-< top-3 insert; ascending processing order keeps lowest index on ties.
__device__ __forceinline__ void ins3(float s, int i, float& b0, int& i0,
                                     float& b1, int& i1, float& b2, int& i2) {
    if (s < b0)      { b2 = b1; i2 = i1; b1 = b0; i1 = i0; b0 = s; i0 = i; }
    else if (s < b1) { b2 = b1; i2 = i1; b1 = s; i1 = i; }
    else if (s < b2) { b2 = s; i2 = i; }
}

#define HMMA16(d0, d1, a0, a1, a2, a3, b0, b1) \
    asm volatile("mma.sync.aligned.m16n8k16.row.col.f16.f16.f16.f16 " \
        "{%0,%1}, {%2,%3,%4,%5}, {%6,%7}, {%0,%1};" \
        : "+r"(d0), "+r"(d1) \
        : "r"(a0), "r"(a1), "r"(a2), "r"(a3), "r"(b0), "r"(b1))

// ---- Kernel B: f16-accum HMMA scoring + rare-branch top-3; flagged -> worklist ----
__global__ __launch_bounds__(TPB, 2) void vq_main(const float* __restrict__ inputs,
                                                  const float* __restrict__ codebook,
                                                  float* __restrict__ out) {
    extern __shared__ char smem[];
    unsigned* Aw   = reinterpret_cast<unsigned*>(smem + SM_A);
    unsigned* Bw   = reinterpret_cast<unsigned*>(smem + SM_B);
    unsigned* cn16 = reinterpret_cast<unsigned*>(smem + SM_CN);

    const int tid  = threadIdx.x;
    const int wid  = tid >> 5;
    const int lane = tid & 31;
    const int g    = lane >> 2;
    const int q    = lane & 3;
    const int tok_base = blockIdx.x * TOKS;

    // Stage A (tokens -> f16 smem), cn16, B tile 0.
    {
        const int tok = tid & 127;
        const int hs  = tid >> 7;
        const int T   = tok_base + tok;
        const int b   = T >> 12, hw = T & (HWSZ - 1);
        const float* xin = inputs + (b * D + hs * 32) * HWSZ + hw;
        unsigned* dst = Aw + tok * ASTRIDE_W + hs * 16;
#pragma unroll
        for (int j = 0; j < 16; ++j) {
            __half2 h = __floats2half2_rn(xin[(2 * j) * HWSZ], xin[(2 * j + 1) * HWSZ]);
            dst[j] = *reinterpret_cast<unsigned*>(&h);
        }
        const unsigned* cns = reinterpret_cast<const unsigned*>(g_cn16);
        for (int i = tid; i < KCODES / 2; i += TPB) cn16[i] = cns[i];
        const uint4* src = reinterpret_cast<const uint4*>(g_cb16);
        uint4* dstB = reinterpret_cast<uint4*>(smem + SM_B);
        for (int i = tid; i < TILE * 8; i += TPB)
            dstB[(i >> 3) * 9 + (i & 7)] = src[i];
    }
    __syncthreads();

    unsigned a[4][4];
    {
        const int rA = (wid * 16 + g) * ASTRIDE_W;
#pragma unroll
        for (int k = 0; k < 4; ++k) {
            a[k][0] = Aw[rA + k * 8 + q];
            a[k][1] = Aw[rA + 8 * ASTRIDE_W + k * 8 + q];
            a[k][2] = Aw[rA + k * 8 + q + 4];
            a[k][3] = Aw[rA + 8 * ASTRIDE_W + k * 8 + q + 4];
        }
    }

    float bA0 = 3.4e38f, bA1 = 3.4e38f, bA2 = 3.4e38f;
    float bB0 = 3.4e38f, bB1 = 3.4e38f, bB2 = 3.4e38f;
    int   iA0 = 0x7fffffff, iA1 = 0x7fffffff, iA2 = 0x7fffffff;
    int   iB0 = 0x7fffffff, iB1 = 0x7fffffff, iB2 = 0x7fffffff;

#pragma unroll 1
    for (int tile = 0; tile < 2; ++tile) {
        if (tile == 1) {
            __syncthreads();
            const uint4* src = reinterpret_cast<const uint4*>(g_cb16) + TILE * 8;
            uint4* dstB = reinterpret_cast<uint4*>(smem + SM_B);
            for (int i = tid; i < TILE * 8; i += TPB)
                dstB[(i >> 3) * 9 + (i & 7)] = src[i];
            __syncthreads();
        }
        const int tbase = tile * TILE;
#pragma unroll 4
        for (int ch = 0; ch < TILE / 8; ++ch) {
            const unsigned* bp = Bw + (ch * 8 + g) * BSTRIDE_W + q;
            const int g0 = tbase + ch * 8 + 2 * q;
            unsigned cpair = cn16[g0 >> 1];          // {cn[g0], cn[g0+1]} f16x2
            unsigned d0 = cpair, d1 = cpair;
#pragma unroll
            for (int k = 0; k < 4; ++k)
                HMMA16(d0, d1, a[k][0], a[k][1], a[k][2], a[k][3],
                       bp[k * 8], bp[k * 8 + 4]);
            __half2 pA = *reinterpret_cast<__half2*>(&d0);
            __half2 pB = *reinterpret_cast<__half2*>(&d1);
            float mA = __half2float(__hmin(__low2half(pA), __high2half(pA)));
            float mB = __half2float(__hmin(__low2half(pB), __high2half(pB)));
            if (mA <= bA2 || mB <= bB2) {            // rare branch (top-3 thresholds)
                float a0f = __half2float(__low2half(pA));
                float a1f = __half2float(__high2half(pA));
                float b0f = __half2float(__low2half(pB));
                float b1f = __half2float(__high2half(pB));
                ins3(a0f, g0,     bA0, iA0, bA1, iA1, bA2, iA2);
                ins3(a1f, g0 + 1, bA0, iA0, bA1, iA1, bA2, iA2);
                ins3(b0f, g0,     bB0, iB0, bB1, iB1, bB2, iB2);
                ins3(b1f, g0 + 1, bB0, iB0, bB1, iB1, bB2, iB2);
            }
        }
    }

#pragma unroll 1
    for (int row = 0; row < 2; ++row) {
        const int T  = tok_base + wid * 16 + g + row * 8;
        const int b  = T >> 12, hw = T & (HWSZ - 1);
        float lb0 = row ? bB0 : bA0, lb1 = row ? bB1 : bA1;
        int   li0 = row ? iB0 : iA0, li1 = row ? iB1 : iA1;
        int   li2 = row ? iB2 : iA2;
        float m0 = lb0, m1 = lb1; int j0 = li0, j1 = li1;
        butterfly2(m0, j0, m1, j1);                  // quad-level noisy top-2

        unsigned myc01 = (unsigned)li0 | ((unsigned)li1 << 16);
        unsigned myc2  = (unsigned)li2;
        unsigned qb = lane & ~3u;
        uint4 fc0 = make_uint4(__shfl_sync(0xffffffffu, myc01, qb + 0),
                               __shfl_sync(0xffffffffu, myc01, qb + 1),
                               __shfl_sync(0xffffffffu, myc01, qb + 2),
                               __shfl_sync(0xffffffffu, myc01, qb + 3));
        uint4 fc1 = make_uint4(__shfl_sync(0xffffffffu, myc2, qb + 0),
                               __shfl_sync(0xffffffffu, myc2, qb + 1),
                               __shfl_sync(0xffffffffu, myc2, qb + 2),
                               __shfl_sync(0xffffffffu, myc2, qb + 3));

        if (m1 - m0 < MARGIN) {
            if (q == 0) {
                int wv = atomicAdd(&g_nflag, 1);
                g_ftok[wv] = T;
                g_fc0[wv]  = fc0;
                g_fc1[wv]  = fc1;
            }
        } else {
            const int bestk = j0;
            if (q == 0) atomicAdd(&g_counts[bestk], 1);
            const float* xt = inputs + (b * D) * HWSZ + hw;
            const float* qp = codebook + bestk * D;
            float* op = out + (b * D) * HWSZ + hw;
#pragma unroll
            for (int m = 0; m < 16; ++m) {
                int c = q * 16 + m;
                float xv = __ldg(&xt[c * HWSZ]);
                op[c * HWSZ] = xv + (__ldg(&qp[c]) - xv);
            }
        }
    }
}

// ---- Kernel C: exact rescue (12 candidates) + perplexity + replay-state reset ----
__global__ void vq_rescue_perp(const float* __restrict__ inputs,
                               const float* __restrict__ codebook,
                               float* __restrict__ out, int out_size) {
    const int n = g_nflag;
    for (int i = blockIdx.x * blockDim.x + threadIdx.x; i < n;
         i += gridDim.x * blockDim.x) {
        const int T = g_ftok[i];
        const uint4 c0w = g_fc0[i];
        const uint4 c1w = g_fc1[i];
        int cand[12] = {
            (int)(c0w.x & 0xffff), (int)(c0w.x >> 16), (int)(c1w.x & 0xffff),
            (int)(c0w.y & 0xffff), (int)(c0w.y >> 16), (int)(c1w.y & 0xffff),
            (int)(c0w.z & 0xffff), (int)(c0w.z >> 16), (int)(c1w.z & 0xffff),
            (int)(c0w.w & 0xffff), (int)(c0w.w >> 16), (int)(c1w.w & 0xffff) };
        const int b = T >> 12, hw = T & (HWSZ - 1);
        const float* xt = inputs + (b * D) * HWSZ + hw;
        float xa[D];
#pragma unroll
        for (int d2 = 0; d2 < D; ++d2) xa[d2] = __ldg(&xt[d2 * HWSZ]);

        float e0 = 3.4e38f, e1 = 3.4e38f;
        int   k0 = 0x7fffffff, k1 = 0x7fffffff;
#pragma unroll
        for (int j = 0; j < 12; ++j) {
            int k = cand[j];
            float e = fp32_score(codebook, k, xa);
            if (e < e0 || (e == e0 && k < k0)) { e1 = e0; k1 = k0; e0 = e; k0 = k; }
            else if (e < e1 || (e == e1 && k < k1)) { e1 = e; k1 = k; }
        }
        int bestk = k0;
        if (e1 - e0 < RESCUE) {                      // fp64 grid rescue (R2-proven)
            double A = 0.0;
#pragma unroll
            for (int d2 = 0; d2 < D; ++d2) A += (double)(xa[d2] * xa[d2]);
            float A32 = (float)A;
            int klo = min(k0, k1), khi = max(k0, k1);
            float dlo = ref_score(codebook, klo, xa, A32);
            float dhi = ref_score(codebook, khi, xa, A32);
            bestk = (dhi < dlo) ? khi : klo;
        }
        atomicAdd(&g_counts[bestk], 1);
        const float* qp = codebook + bestk * D;
        float* op = out + (b * D) * HWSZ + hw;
#pragma unroll
        for (int c = 0; c < D; ++c) {
            float xv = xa[c];
            op[c * HWSZ] = xv + (__ldg(&qp[c]) - xv);
        }
    }

    // Last CTA: perplexity from final counts, then reset replay state.
    __shared__ int sflag;
    __shared__ float red[32];
    __threadfence();
    __syncthreads();
    if (threadIdx.x == 0) sflag = (atomicAdd(&g_done, 1) == gridDim.x - 1);
    __syncthreads();
    if (!sflag) return;
    __threadfence();

    const int t = threadIdx.x;              // 128 threads, 8 bins each
    float v = 0.f;
#pragma unroll
    for (int j = 0; j < 8; ++j) {
        float e = (float)g_counts[t * 8 + j] * (1.0f / (float)NTOK);
        v += e * logf(e + 1e-10f);
    }
#pragma unroll
    for (int o = 16; o > 0; o >>= 1) v += __shfl_down_sync(0xffffffffu, v, o);
    if ((t & 31) == 0) red[t >> 5] = v;
    __syncthreads();
    if (t == 0) {
        float s = red[0] + red[1] + red[2] + red[3];
        if (out_size > NTOK * D) out[NTOK * D] = expf(-s);
    }
    __syncthreads();
#pragma unroll
    for (int j = 0; j < 8; ++j) g_counts[t * 8 + j] = 0;
    if (t == 0) { g_nflag = 0; g_done = 0; }
}

extern "C" void kernel_launch(void* const* d_in, const int* in_sizes, int n_in,
                              void* d_out, int out_size) {
    const float* inputs   = (const float*)d_in[0];
    const float* codebook = (const float*)d_in[1];
    float*       out      = (float*)d_out;

    cudaFuncSetAttribute(vq_main, cudaFuncAttributeMaxDynamicSharedMemorySize, SM_TOTAL);

    vq_prep<<<KCODES / 8, TPB>>>(codebook);
    vq_nop<<<1, 1>>>();
    vq_nop<<<1, 1>>>();
    vq_main<<<NTOK / TOKS, TPB, SM_TOTAL>>>(inputs, codebook, out);
    vq_rescue_perp<<<RGRID, 128>>>(inputs, codebook, out, out_size);
}

// round 9
// speedup vs baseline: 1.7334x; 1.7334x over previous
#include <cuda_runtime.h>
#include <cuda_fp16.h>
#include <math.h>

namespace {
constexpr int KCODES = 1024;
constexpr int D      = 64;
constexpr int HWSZ   = 64 * 64;
constexpr int NTOK   = 32 * HWSZ;        // 131072
constexpr int TPB    = 256;              // 8 warps, 128 tokens/CTA
constexpr int TOKS   = 128;
constexpr int TILE   = 512;              // codes per smem B tile
constexpr float MARGIN = 0.05f;          // f16 input err (<=0.02) + key quant (<=2e-3), 2-sided
constexpr float RESCUE = 1e-4f;          // fp64 grid-rescue threshold (R2-proven)

constexpr int ASTRIDE_W = 36;            // A row stride in u32 words (144B)
constexpr int SM_A  = 0;                 // 128 * 144B = 18432
constexpr int SM_B  = 18432;             // 512 codes * 128B fragment-packed = 65536
constexpr int SM_CN = 83968;             // 1024 f32 = 4096
constexpr int SM_TOTAL = 88064;
constexpr int RGRID = 256;
}

__device__ float    g_cnorm[KCODES];
__device__ int      g_counts[KCODES];
__device__ unsigned g_cbf[KCODES * 32];    // f16x2 of (-2c), MMA-fragment-packed
__device__ int      g_nflag;
__device__ int      g_done;
__device__ int      g_ftok[NTOK];
__device__ uint4    g_fcand[NTOK];         // 8 candidate ids: 4 x (u16|u16)

__global__ void vq_nop() {}

// ---- Kernel A: warp-per-code prep: norms + fragment-packed f16(-2c) ----
// Fragment order: lane (g=code%8? no: within-chunk row g, quad q) needs words
// {q + 4j, j=0..7} of its code row. Store code k's word w at
//   chunk(k/8)*256 + ((k%8)*4 + (w%4))*8 + (w/4).
__global__ void vq_prep(const float* __restrict__ codebook) {
    const int k    = (blockIdx.x * blockDim.x + threadIdx.x) >> 5;
    const int w    = threadIdx.x & 31;
    if (k >= KCODES) return;
    float a = codebook[k * D + 2 * w];
    float b = codebook[k * D + 2 * w + 1];
    __half2 h = __floats2half2_rn(-2.0f * a, -2.0f * b);
    g_cbf[(k >> 3) * 256 + ((k & 7) * 4 + (w & 3)) * 8 + (w >> 2)] =
        *reinterpret_cast<unsigned*>(&h);
    float p = fmaf(a, a, b * b);
#pragma unroll
    for (int o = 16; o > 0; o >>= 1) p += __shfl_xor_sync(0xffffffffu, p, o);
    if (w == 0) g_cnorm[k] = p;
}

// Exact emulation of the reference's rounded score (proven in round 2).
__device__ __forceinline__ float ref_score(const float* __restrict__ cb, int k,
                                           const float* x, float A32) {
    const float* cp = cb + k * D;
    double dot = 0.0, C = 0.0;
#pragma unroll
    for (int i = 0; i < D; ++i) {
        float cv = cp[i];
        dot += (double)x[i] * (double)cv;
        C   += (double)(cv * cv);
    }
    float t1 = (float)dot;
    float t2 = A32 - 2.0f * t1;
    return t2 + (float)C;
}

__device__ __forceinline__ float fp32_score(const float* __restrict__ cb, int k,
                                            const float* x) {
    const float* cp = cb + k * D;
    float d0 = 0.f, d1 = 0.f, d2 = 0.f, d3 = 0.f;
#pragma unroll
    for (int i = 0; i < D / 4; ++i) {
        d0 = fmaf(x[4 * i + 0], __ldg(&cp[4 * i + 0]), d0);
        d1 = fmaf(x[4 * i + 1], __ldg(&cp[4 * i + 1]), d1);
        d2 = fmaf(x[4 * i + 2], __ldg(&cp[4 * i + 2]), d2);
        d3 = fmaf(x[4 * i + 3], __ldg(&cp[4 * i + 3]), d3);
    }
    return g_cnorm[k] - 2.0f * ((d0 + d1) + (d2 + d3));
}

// Orderable key: monotone in score; low 10 bits carry the code index so
// umin() resolves ties to the lowest index (argmin semantics).
__device__ __forceinline__ unsigned score_key(float s, int idx) {
    unsigned u = __float_as_uint(s);
    unsigned m = (unsigned)(((int)u) >> 31);
    unsigned key = u ^ (m | 0x80000000u);
    return (key & ~1023u) | (unsigned)idx;
}
__device__ __forceinline__ float key_score(unsigned k) {
    return (k & 0x80000000u) ? __uint_as_float(k ^ 0x80000000u)
                             : __uint_as_float(~k);
}
__device__ __forceinline__ void kins2(unsigned kv, unsigned& k0, unsigned& k1) {
    k1 = umin(k1, umax(k0, kv));
    k0 = umin(k0, kv);
}

#define HMMA(c0, c1, c2, c3, a0, a1, a2, a3, b0, b1) \
    asm volatile("mma.sync.aligned.m16n8k16.row.col.f32.f16.f16.f32 " \
        "{%0,%1,%2,%3}, {%4,%5,%6,%7}, {%8,%9}, {%0,%1,%2,%3};" \
        : "+f"(c0), "+f"(c1), "+f"(c2), "+f"(c3) \
        : "r"(a0), "r"(a1), "r"(a2), "r"(a3), "r"(b0), "r"(b1))

// ---- Kernel B: HMMA scoring + branchless key top-2; flagged -> worklist ----
__global__ __launch_bounds__(TPB, 2) void vq_main(const float* __restrict__ inputs,
                                                  const float* __restrict__ codebook,
                                                  float* __restrict__ out) {
    extern __shared__ char smem[];
    unsigned* Aw = reinterpret_cast<unsigned*>(smem + SM_A);
    float*    cn = reinterpret_cast<float*>(smem + SM_CN);

    const int tid  = threadIdx.x;
    const int wid  = tid >> 5;
    const int lane = tid & 31;
    const int g    = lane >> 2;
    const int q    = lane & 3;
    const int tok_base = blockIdx.x * TOKS;

    // Stage A (tokens -> f16 smem), cn, B tile 0 (linear fragment-packed copy).
    {
        const int tok = tid & 127;
        const int hs  = tid >> 7;
        const int T   = tok_base + tok;
        const int b   = T >> 12, hw = T & (HWSZ - 1);
        const float* xin = inputs + (b * D + hs * 32) * HWSZ + hw;
        unsigned* dst = Aw + tok * ASTRIDE_W + hs * 16;
#pragma unroll
        for (int j = 0; j < 16; ++j) {
            __half2 h = __floats2half2_rn(xin[(2 * j) * HWSZ], xin[(2 * j + 1) * HWSZ]);
            dst[j] = *reinterpret_cast<unsigned*>(&h);
        }
        for (int i = tid; i < KCODES; i += TPB) cn[i] = g_cnorm[i];
        const uint4* src = reinterpret_cast<const uint4*>(g_cbf);
        uint4* dstB = reinterpret_cast<uint4*>(smem + SM_B);
        for (int i = tid; i < TILE * 8; i += TPB) dstB[i] = src[i];
    }
    __syncthreads();

    unsigned a[4][4];
    {
        const int rA = (wid * 16 + g) * ASTRIDE_W;
#pragma unroll
        for (int k = 0; k < 4; ++k) {
            a[k][0] = Aw[rA + k * 8 + q];
            a[k][1] = Aw[rA + 8 * ASTRIDE_W + k * 8 + q];
            a[k][2] = Aw[rA + k * 8 + q + 4];
            a[k][3] = Aw[rA + 8 * ASTRIDE_W + k * 8 + q + 4];
        }
    }

    unsigned kA0 = 0xffffffffu, kA1 = 0xffffffffu;
    unsigned kB0 = 0xffffffffu, kB1 = 0xffffffffu;

#pragma unroll 1
    for (int tile = 0; tile < 2; ++tile) {
        if (tile == 1) {
            __syncthreads();
            const uint4* src = reinterpret_cast<const uint4*>(g_cbf) + TILE * 8;
            uint4* dstB = reinterpret_cast<uint4*>(smem + SM_B);
            for (int i = tid; i < TILE * 8; i += TPB) dstB[i] = src[i];
            __syncthreads();
        }
        const int tbase = tile * TILE;
#pragma unroll 4
        for (int ch = 0; ch < TILE / 8; ++ch) {
            const uint4* bp = reinterpret_cast<const uint4*>(smem + SM_B)
                              + ch * 64 + lane * 2;
            uint4 lo = bp[0];                 // k-steps 0,1 fragments
            uint4 hi = bp[1];                 // k-steps 2,3 fragments
            const int g0 = tbase + ch * 8 + 2 * q;
            float2 cnv = *reinterpret_cast<const float2*>(&cn[g0]);
            float c0 = cnv.x, c1 = cnv.y, c2 = cnv.x, c3 = cnv.y;
            HMMA(c0, c1, c2, c3, a[0][0], a[0][1], a[0][2], a[0][3], lo.x, lo.y);
            HMMA(c0, c1, c2, c3, a[1][0], a[1][1], a[1][2], a[1][3], lo.z, lo.w);
            HMMA(c0, c1, c2, c3, a[2][0], a[2][1], a[2][2], a[2][3], hi.x, hi.y);
            HMMA(c0, c1, c2, c3, a[3][0], a[3][1], a[3][2], a[3][3], hi.z, hi.w);
            kins2(score_key(c0, g0),     kA0, kA1);
            kins2(score_key(c1, g0 + 1), kA0, kA1);
            kins2(score_key(c2, g0),     kB0, kB1);
            kins2(score_key(c3, g0 + 1), kB0, kB1);
        }
    }

#pragma unroll 1
    for (int row = 0; row < 2; ++row) {
        const int T  = tok_base + wid * 16 + g + row * 8;
        const int b  = T >> 12, hw = T & (HWSZ - 1);
        unsigned lk0 = row ? kB0 : kA0, lk1 = row ? kB1 : kA1;
        unsigned m0 = lk0, m1 = lk1;
#pragma unroll
        for (int d = 1; d <= 2; d <<= 1) {          // quad top-2 merge on keys
            unsigned r0 = __shfl_xor_sync(0xffffffffu, m0, d);
            unsigned r1 = __shfl_xor_sync(0xffffffffu, m1, d);
            kins2(r0, m0, m1);
            m1 = umin(m1, r1);                      // r1 >= r0 >= m0 already
        }

        // Gather the quad's 8 local candidate indices.
        unsigned myc = (lk0 & 1023u) | ((lk1 & 1023u) << 16);
        unsigned qb  = lane & ~3u;
        uint4 fc = make_uint4(__shfl_sync(0xffffffffu, myc, qb + 0),
                              __shfl_sync(0xffffffffu, myc, qb + 1),
                              __shfl_sync(0xffffffffu, myc, qb + 2),
                              __shfl_sync(0xffffffffu, myc, qb + 3));

        if (key_score(m1) - key_score(m0) < MARGIN) {   // defer to rescue kernel
            if (q == 0) {
                int wv = atomicAdd(&g_nflag, 1);
                g_ftok[wv]  = T;
                g_fcand[wv] = fc;
            }
        } else {                                        // safe: winner exact
            const int bestk = (int)(m0 & 1023u);
            if (q == 0) atomicAdd(&g_counts[bestk], 1);
            const float* xt = inputs + (b * D) * HWSZ + hw;
            const float* qp = codebook + bestk * D;
            float* op = out + (b * D) * HWSZ + hw;
#pragma unroll
            for (int m = 0; m < 16; ++m) {
                int c = q * 16 + m;
                float xv = __ldg(&xt[c * HWSZ]);
                op[c * HWSZ] = xv + (__ldg(&qp[c]) - xv);
            }
        }
    }
}

// ---- Kernel C: exact rescue (8 cands) + perplexity + replay-state reset ----
__global__ void vq_rescue_perp(const float* __restrict__ inputs,
                               const float* __restrict__ codebook,
                               float* __restrict__ out, int out_size) {
    const int n = g_nflag;
    for (int i = blockIdx.x * blockDim.x + threadIdx.x; i < n;
         i += gridDim.x * blockDim.x) {
        const int T = g_ftok[i];
        const uint4 cw = g_fcand[i];
        int cand[8] = { (int)(cw.x & 0xffff), (int)(cw.x >> 16),
                        (int)(cw.y & 0xffff), (int)(cw.y >> 16),
                        (int)(cw.z & 0xffff), (int)(cw.z >> 16),
                        (int)(cw.w & 0xffff), (int)(cw.w >> 16) };
        const int b = T >> 12, hw = T & (HWSZ - 1);
        const float* xt = inputs + (b * D) * HWSZ + hw;
        float xa[D];
#pragma unroll
        for (int d2 = 0; d2 < D; ++d2) xa[d2] = __ldg(&xt[d2 * HWSZ]);

        float e0 = 3.4e38f, e1 = 3.4e38f;
        int   k0 = 0x7fffffff, k1 = 0x7fffffff;
#pragma unroll
        for (int j = 0; j < 8; ++j) {
            int k = cand[j];
            float e = fp32_score(codebook, k, xa);
            if (e < e0 || (e == e0 && k < k0)) { e1 = e0; k1 = k0; e0 = e; k0 = k; }
            else if (e < e1 || (e == e1 && k < k1)) { e1 = e; k1 = k; }
        }
        int bestk = k0;
        if (e1 - e0 < RESCUE) {                      // fp64 grid rescue (R2-proven)
            double A = 0.0;
#pragma unroll
            for (int d2 = 0; d2 < D; ++d2) A += (double)(xa[d2] * xa[d2]);
            float A32 = (float)A;
            int klo = min(k0, k1), khi = max(k0, k1);
            float dlo = ref_score(codebook, klo, xa, A32);
            float dhi = ref_score(codebook, khi, xa, A32);
            bestk = (dhi < dlo) ? khi : klo;
        }
        atomicAdd(&g_counts[bestk], 1);
        const float* qp = codebook + bestk * D;
        float* op = out + (b * D) * HWSZ + hw;
#pragma unroll
        for (int c = 0; c < D; ++c) {
            float xv = xa[c];
            op[c * HWSZ] = xv + (__ldg(&qp[c]) - xv);
        }
    }

    // Last CTA: perplexity from final counts, then reset replay state.
    __shared__ int sflag;
    __shared__ float red[32];
    __threadfence();
    __syncthreads();
    if (threadIdx.x == 0) sflag = (atomicAdd(&g_done, 1) == gridDim.x - 1);
    __syncthreads();
    if (!sflag) return;
    __threadfence();

    const int t = threadIdx.x;              // 128 threads, 8 bins each
    float v = 0.f;
#pragma unroll
    for (int j = 0; j < 8; ++j) {
        float e = (float)g_counts[t * 8 + j] * (1.0f / (float)NTOK);
        v += e * logf(e + 1e-10f);
    }
#pragma unroll
    for (int o = 16; o > 0; o >>= 1) v += __shfl_down_sync(0xffffffffu, v, o);
    if ((t & 31) == 0) red[t >> 5] = v;
    __syncthreads();
    if (t == 0) {
        float s = red[0] + red[1] + red[2] + red[3];
        if (out_size > NTOK * D) out[NTOK * D] = expf(-s);
    }
    __syncthreads();
#pragma unroll
    for (int j = 0; j < 8; ++j) g_counts[t * 8 + j] = 0;
    if (t == 0) { g_nflag = 0; g_done = 0; }
}

extern "C" void kernel_launch(void* const* d_in, const int* in_sizes, int n_in,
                              void* d_out, int out_size) {
    const float* inputs   = (const float*)d_in[0];
    const float* codebook = (const float*)d_in[1];
    float*       out      = (float*)d_out;

    cudaFuncSetAttribute(vq_main, cudaFuncAttributeMaxDynamicSharedMemorySize, SM_TOTAL);

    vq_prep<<<KCODES / 8, TPB>>>(codebook);
    vq_nop<<<1, 1>>>();
    vq_nop<<<1, 1>>>();
    vq_main<<<NTOK / TOKS, TPB, SM_TOTAL>>>(inputs, codebook, out);
    vq_rescue_perp<<<RGRID, 128>>>(inputs, codebook, out, out_size);
}

// round 10
// speedup vs baseline: 2.3767x; 1.3711x over previous
#include <cuda_runtime.h>
#include <cuda_fp16.h>
#include <math.h>

namespace {
constexpr int KCODES = 1024;
constexpr int D      = 64;
constexpr int HWSZ   = 64 * 64;
constexpr int NTOK   = 32 * HWSZ;        // 131072
constexpr int TPB    = 256;              // 8 warps, 32 tokens/warp -> 256 tokens/CTA
constexpr int TOKS   = 256;
constexpr int TILE   = 512;              // codes per smem B tile
constexpr float MARGIN = 0.05f;          // f16 input err (<=0.02/side) + key quant (<=2e-3)
constexpr float RESCUE = 1e-4f;          // fp64 grid-rescue threshold (R2-proven)

constexpr int ASTRIDE_W = 36;            // A row stride in u32 words (144B)
constexpr int SM_A  = 0;                 // 256 * 144B = 36864
constexpr int SM_B  = 36864;             // 512 codes * 128B fragment-packed = 65536
constexpr int SM_CN = 102400;            // 1024 f32 = 4096
constexpr int SM_TOTAL = 106496;
constexpr int RGRID = 128;               // rescue grid (x256 thr = 1024 warps)
}

__device__ float    g_cnorm[KCODES];
__device__ int      g_counts[KCODES];
__device__ unsigned g_cbf[KCODES * 32];    // f16x2 of (-2c), MMA-fragment-packed
__device__ int      g_nflag;
__device__ int      g_done;
__device__ int      g_ftok[NTOK];
__device__ uint4    g_fcand[NTOK];         // 8 candidate ids: 4 x (u16|u16)

__global__ void vq_nop() {}

// ---- Kernel A: warp-per-code prep: norms + fragment-packed f16(-2c) ----
// Code k word w -> chunk(k/8)*256 + ((k%8)*4 + (w%4))*8 + (w/4)   (R9-validated)
__global__ void vq_prep(const float* __restrict__ codebook) {
    const int k = (blockIdx.x * blockDim.x + threadIdx.x) >> 5;
    const int w = threadIdx.x & 31;
    if (k >= KCODES) return;
    float a = codebook[k * D + 2 * w];
    float b = codebook[k * D + 2 * w + 1];
    __half2 h = __floats2half2_rn(-2.0f * a, -2.0f * b);
    g_cbf[(k >> 3) * 256 + ((k & 7) * 4 + (w & 3)) * 8 + (w >> 2)] =
        *reinterpret_cast<unsigned*>(&h);
    float p = fmaf(a, a, b * b);
#pragma unroll
    for (int o = 16; o > 0; o >>= 1) p += __shfl_xor_sync(0xffffffffu, p, o);
    if (w == 0) g_cnorm[k] = p;
}

// Orderable key: monotone in score; low 10 bits carry the code index so
// umin() resolves ties to the lowest index (argmin semantics).
__device__ __forceinline__ unsigned score_key(float s, int idx) {
    unsigned u = __float_as_uint(s);
    unsigned m = (unsigned)(((int)u) >> 31);
    unsigned key = u ^ (m | 0x80000000u);
    return (key & ~1023u) | (unsigned)idx;
}
__device__ __forceinline__ float key_score(unsigned k) {
    return (k & 0x80000000u) ? __uint_as_float(k ^ 0x80000000u)
                             : __uint_as_float(~k);
}
__device__ __forceinline__ void kins2(unsigned kv, unsigned& k0, unsigned& k1) {
    k1 = umin(k1, umax(k0, kv));
    k0 = umin(k0, kv);
}

#define HMMA(c0, c1, c2, c3, a0, a1, a2, a3, b0, b1) \
    asm volatile("mma.sync.aligned.m16n8k16.row.col.f32.f16.f16.f32 " \
        "{%0,%1,%2,%3}, {%4,%5,%6,%7}, {%8,%9}, {%0,%1,%2,%3};" \
        : "+f"(c0), "+f"(c1), "+f"(c2), "+f"(c3) \
        : "r"(a0), "r"(a1), "r"(a2), "r"(a3), "r"(b0), "r"(b1))

// ---- Kernel B: HMMA scoring (2 A-frags/warp) + branchless key top-2 ----
__global__ __launch_bounds__(TPB, 2) void vq_main(const float* __restrict__ inputs,
                                                  const float* __restrict__ codebook,
                                                  float* __restrict__ out) {
    extern __shared__ char smem[];
    unsigned* Aw = reinterpret_cast<unsigned*>(smem + SM_A);
    float*    cn = reinterpret_cast<float*>(smem + SM_CN);

    const int tid  = threadIdx.x;
    const int wid  = tid >> 5;
    const int lane = tid & 31;
    const int g    = lane >> 2;
    const int q    = lane & 3;
    const int tok_base = blockIdx.x * TOKS;

    // Stage A: thread tid stages token tok_base+tid (64 dims -> 32 f16x2 words).
    {
        const int T = tok_base + tid;
        const int b = T >> 12, hw = T & (HWSZ - 1);
        const float* xin = inputs + (b * D) * HWSZ + hw;
        unsigned* dst = Aw + tid * ASTRIDE_W;
#pragma unroll
        for (int j = 0; j < 32; ++j) {
            __half2 h = __floats2half2_rn(xin[(2 * j) * HWSZ], xin[(2 * j + 1) * HWSZ]);
            dst[j] = *reinterpret_cast<unsigned*>(&h);
        }
        for (int i = tid; i < KCODES; i += TPB) cn[i] = g_cnorm[i];
        const uint4* src = reinterpret_cast<const uint4*>(g_cbf);
        uint4* dstB = reinterpret_cast<uint4*>(smem + SM_B);
        for (int i = tid; i < TILE * 8; i += TPB) dstB[i] = src[i];
    }
    __syncthreads();

    // Two A fragments: tokens wid*32 + f*16 + {g, g+8}.
    unsigned a[2][4][4];
#pragma unroll
    for (int f = 0; f < 2; ++f) {
        const int r0 = (wid * 32 + f * 16 + g) * ASTRIDE_W;
        const int r1 = (wid * 32 + f * 16 + 8 + g) * ASTRIDE_W;
#pragma unroll
        for (int k = 0; k < 4; ++k) {
            a[f][k][0] = Aw[r0 + k * 8 + q];
            a[f][k][1] = Aw[r1 + k * 8 + q];
            a[f][k][2] = Aw[r0 + k * 8 + q + 4];
            a[f][k][3] = Aw[r1 + k * 8 + q + 4];
        }
    }

    unsigned kA0 = 0xffffffffu, kA1 = 0xffffffffu;   // token w*32+g
    unsigned kB0 = 0xffffffffu, kB1 = 0xffffffffu;   // token w*32+8+g
    unsigned kC0 = 0xffffffffu, kC1 = 0xffffffffu;   // token w*32+16+g
    unsigned kD0 = 0xffffffffu, kD1 = 0xffffffffu;   // token w*32+24+g

#pragma unroll 1
    for (int tile = 0; tile < 2; ++tile) {
        if (tile == 1) {
            __syncthreads();
            const uint4* src = reinterpret_cast<const uint4*>(g_cbf) + TILE * 8;
            uint4* dstB = reinterpret_cast<uint4*>(smem + SM_B);
            for (int i = tid; i < TILE * 8; i += TPB) dstB[i] = src[i];
            __syncthreads();
        }
        const int tbase = tile * TILE;
#pragma unroll 2
        for (int ch = 0; ch < TILE / 8; ++ch) {
            const uint4* bp = reinterpret_cast<const uint4*>(smem + SM_B)
                              + ch * 64 + lane * 2;
            uint4 lo = bp[0];
            uint4 hi = bp[1];
            const int g0 = tbase + ch * 8 + 2 * q;
            float2 cnv = *reinterpret_cast<const float2*>(&cn[g0]);
            float c0 = cnv.x, c1 = cnv.y, c2 = cnv.x, c3 = cnv.y;
            float c4 = cnv.x, c5 = cnv.y, c6 = cnv.x, c7 = cnv.y;
            HMMA(c0, c1, c2, c3, a[0][0][0], a[0][0][1], a[0][0][2], a[0][0][3], lo.x, lo.y);
            HMMA(c4, c5, c6, c7, a[1][0][0], a[1][0][1], a[1][0][2], a[1][0][3], lo.x, lo.y);
            HMMA(c0, c1, c2, c3, a[0][1][0], a[0][1][1], a[0][1][2], a[0][1][3], lo.z, lo.w);
            HMMA(c4, c5, c6, c7, a[1][1][0], a[1][1][1], a[1][1][2], a[1][1][3], lo.z, lo.w);
            HMMA(c0, c1, c2, c3, a[0][2][0], a[0][2][1], a[0][2][2], a[0][2][3], hi.x, hi.y);
            HMMA(c4, c5, c6, c7, a[1][2][0], a[1][2][1], a[1][2][2], a[1][2][3], hi.x, hi.y);
            HMMA(c0, c1, c2, c3, a[0][3][0], a[0][3][1], a[0][3][2], a[0][3][3], hi.z, hi.w);
            HMMA(c4, c5, c6, c7, a[1][3][0], a[1][3][1], a[1][3][2], a[1][3][3], hi.z, hi.w);
            kins2(score_key(c0, g0),     kA0, kA1);
            kins2(score_key(c1, g0 + 1), kA0, kA1);
            kins2(score_key(c2, g0),     kB0, kB1);
            kins2(score_key(c3, g0 + 1), kB0, kB1);
            kins2(score_key(c4, g0),     kC0, kC1);
            kins2(score_key(c5, g0 + 1), kC0, kC1);
            kins2(score_key(c6, g0),     kD0, kD1);
            kins2(score_key(c7, g0 + 1), kD0, kD1);
        }
    }

#pragma unroll 1
    for (int row = 0; row < 4; ++row) {
        const int T  = tok_base + wid * 32 + row * 8 + g;
        const int b  = T >> 12, hw = T & (HWSZ - 1);
        unsigned lk0 = (row == 0) ? kA0 : (row == 1) ? kB0 : (row == 2) ? kC0 : kD0;
        unsigned lk1 = (row == 0) ? kA1 : (row == 1) ? kB1 : (row == 2) ? kC1 : kD1;
        unsigned m0 = lk0, m1 = lk1;
#pragma unroll
        for (int d = 1; d <= 2; d <<= 1) {          // quad top-2 merge on keys
            unsigned r0 = __shfl_xor_sync(0xffffffffu, m0, d);
            unsigned r1 = __shfl_xor_sync(0xffffffffu, m1, d);
            kins2(r0, m0, m1);
            m1 = umin(m1, r1);
        }

        unsigned myc = (lk0 & 1023u) | ((lk1 & 1023u) << 16);
        unsigned qb  = lane & ~3u;
        uint4 fc = make_uint4(__shfl_sync(0xffffffffu, myc, qb + 0),
                              __shfl_sync(0xffffffffu, myc, qb + 1),
                              __shfl_sync(0xffffffffu, myc, qb + 2),
                              __shfl_sync(0xffffffffu, myc, qb + 3));

        if (key_score(m1) - key_score(m0) < MARGIN) {   // defer to rescue kernel
            if (q == 0) {
                int wv = atomicAdd(&g_nflag, 1);
                g_ftok[wv]  = T;
                g_fcand[wv] = fc;
            }
        } else {                                        // safe: winner exact
            const int bestk = (int)(m0 & 1023u);
            if (q == 0) atomicAdd(&g_counts[bestk], 1);
            const float* xt = inputs + (b * D) * HWSZ + hw;
            const float* qp = codebook + bestk * D;
            float* op = out + (b * D) * HWSZ + hw;
#pragma unroll
            for (int m = 0; m < 16; ++m) {
                int c = q * 16 + m;
                float xv = __ldg(&xt[c * HWSZ]);
                op[c * HWSZ] = xv + (__ldg(&qp[c]) - xv);
            }
        }
    }
}

__device__ __forceinline__ float wsumf(float p) {
#pragma unroll
    for (int o = 16; o > 0; o >>= 1) p += __shfl_xor_sync(0xffffffffu, p, o);
    return p;      // identical value on every lane (xor butterfly)
}
__device__ __forceinline__ double wsumd(double p) {
#pragma unroll
    for (int o = 16; o > 0; o >>= 1) p += __shfl_xor_sync(0xffffffffu, p, o);
    return p;
}

// ---- Kernel C: warp-per-token exact rescue + perplexity + replay-state reset ----
__global__ void vq_rescue_perp(const float* __restrict__ inputs,
                               const float* __restrict__ codebook,
                               float* __restrict__ out, int out_size) {
    const int n    = g_nflag;
    const int gw   = (blockIdx.x * blockDim.x + threadIdx.x) >> 5;
    const int lane = threadIdx.x & 31;
    const int nw   = (gridDim.x * blockDim.x) >> 5;

    for (int i = gw; i < n; i += nw) {
        const int T = g_ftok[i];
        const uint4 cw = g_fcand[i];
        int cand[8] = { (int)(cw.x & 0xffff), (int)(cw.x >> 16),
                        (int)(cw.y & 0xffff), (int)(cw.y >> 16),
                        (int)(cw.z & 0xffff), (int)(cw.z >> 16),
                        (int)(cw.w & 0xffff), (int)(cw.w >> 16) };
        const int b = T >> 12, hw = T & (HWSZ - 1);
        const float* xt = inputs + (b * D) * HWSZ + hw;
        // Lane owns dims {2*lane, 2*lane+1}.
        float x0 = __ldg(&xt[(2 * lane) * HWSZ]);
        float x1 = __ldg(&xt[(2 * lane + 1) * HWSZ]);

        float e0 = 3.4e38f, e1 = 3.4e38f;
        int   k0 = 0x7fffffff, k1 = 0x7fffffff;
#pragma unroll
        for (int j = 0; j < 8; ++j) {
            int k = cand[j];
            float2 cv = *reinterpret_cast<const float2*>(codebook + k * D + 2 * lane);
            float e = g_cnorm[k] - 2.0f * wsumf(fmaf(x0, cv.x, x1 * cv.y));
            if (e < e0 || (e == e0 && k < k0)) { e1 = e0; k1 = k0; e0 = e; k0 = k; }
            else if (e < e1 || (e == e1 && k < k1)) { e1 = e; k1 = k; }
        }
        int bestk = k0;
        if (e1 - e0 < RESCUE) {                      // fp64 grid rescue (R2-proven)
            double A = wsumd((double)(x0 * x0) + (double)(x1 * x1));
            float A32 = (float)A;
            int klo = min(k0, k1), khi = max(k0, k1);
            float dsc[2];
#pragma unroll
            for (int j = 0; j < 2; ++j) {
                int k = j ? khi : klo;
                float2 cv = *reinterpret_cast<const float2*>(codebook + k * D + 2 * lane);
                double dot = wsumd((double)x0 * (double)cv.x + (double)x1 * (double)cv.y);
                double C   = wsumd((double)(cv.x * cv.x) + (double)(cv.y * cv.y));
                float t1 = (float)dot;
                float t2 = A32 - 2.0f * t1;
                dsc[j] = t2 + (float)C;
            }
            bestk = (dsc[1] < dsc[0]) ? khi : klo;
        }
        if (lane == 0) atomicAdd(&g_counts[bestk], 1);
        float2 qv = *reinterpret_cast<const float2*>(codebook + bestk * D + 2 * lane);
        float* op = out + (b * D) * HWSZ + hw;
        op[(2 * lane) * HWSZ]     = x0 + (qv.x - x0);
        op[(2 * lane + 1) * HWSZ] = x1 + (qv.y - x1);
    }

    // Last CTA: perplexity from final counts, then reset replay state.
    __shared__ int sflag;
    __shared__ float red[8];
    __threadfence();
    __syncthreads();
    if (threadIdx.x == 0) sflag = (atomicAdd(&g_done, 1) == gridDim.x - 1);
    __syncthreads();
    if (!sflag) return;
    __threadfence();

    const int t = threadIdx.x;              // 256 threads, 4 bins each
    float v = 0.f;
#pragma unroll
    for (int j = 0; j < 4; ++j) {
        float e = (float)g_counts[t * 4 + j] * (1.0f / (float)NTOK);
        v += e * logf(e + 1e-10f);
    }
#pragma unroll
    for (int o = 16; o > 0; o >>= 1) v += __shfl_down_sync(0xffffffffu, v, o);
    if ((t & 31) == 0) red[t >> 5] = v;
    __syncthreads();
    if (t == 0) {
        float s = 0.f;
#pragma unroll
        for (int j = 0; j < 8; ++j) s += red[j];
        if (out_size > NTOK * D) out[NTOK * D] = expf(-s);
    }
    __syncthreads();
#pragma unroll
    for (int j = 0; j < 4; ++j) g_counts[t * 4 + j] = 0;
    if (t == 0) { g_nflag = 0; g_done = 0; }
}

extern "C" void kernel_launch(void* const* d_in, const int* in_sizes, int n_in,
                              void* d_out, int out_size) {
    const float* inputs   = (const float*)d_in[0];
    const float* codebook = (const float*)d_in[1];
    float*       out      = (float*)d_out;

    cudaFuncSetAttribute(vq_main, cudaFuncAttributeMaxDynamicSharedMemorySize, SM_TOTAL);

    vq_prep<<<KCODES / 8, TPB>>>(codebook);
    vq_nop<<<1, 1>>>();
    vq_nop<<<1, 1>>>();
    vq_main<<<NTOK / TOKS, TPB, SM_TOTAL>>>(inputs, codebook, out);
    vq_rescue_perp<<<RGRID, TPB>>>(inputs, codebook, out, out_size);
}

// round 11
// speedup vs baseline: 2.3772x; 1.0002x over previous
#include <cuda_runtime.h>
#include <cuda_fp16.h>
#include <math.h>

namespace {
constexpr int KCODES = 1024;
constexpr int D      = 64;
constexpr int HWSZ   = 64 * 64;
constexpr int NTOK   = 32 * HWSZ;        // 131072
constexpr int TPB    = 256;              // 8 warps, 32 tokens/warp -> 256 tokens/CTA
constexpr int TOKS   = 256;
constexpr int TILE   = 256;              // codes per smem B tile (4 tiles)
constexpr float BIAS   = 128.0f;         // folded into staged cn; makes scores > 0
constexpr float MARGIN = 0.06f;          // f16 err (<=0.04) + key quant (<=0.016×2 sided)
constexpr float RESCUE = 1e-4f;          // fp64 grid-rescue threshold (R2-proven)

constexpr int ASTRIDE_W = 36;            // A row stride in u32 words (144B)
constexpr int SM_A  = 0;                 // 256 * 144B = 36864
constexpr int SM_B  = 36864;             // 256 codes * 128B fragment-packed = 32768
constexpr int SM_CN = 69632;             // 1024 f32 = 4096
constexpr int SM_TOTAL = 73728;          // x3 CTAs = 216 KB <= 228 KB
constexpr int RGRID = 128;
}

__device__ float    g_cnorm[KCODES];
__device__ int      g_counts[KCODES];
__device__ unsigned g_cbf[KCODES * 32];    // f16x2 of (-2c), MMA-fragment-packed
__device__ int      g_nflag;
__device__ int      g_done;
__device__ int      g_ftok[NTOK];
__device__ uint4    g_fcand[NTOK];         // 8 candidate ids: 4 x (u16|u16)

__global__ void vq_nop() {}

// ---- Kernel A: warp-per-code prep: norms + fragment-packed f16(-2c) ----
// Code k word w -> chunk(k/8)*256 + ((k%8)*4 + (w%4))*8 + (w/4)   (R9-validated)
__global__ void vq_prep(const float* __restrict__ codebook) {
    const int k = (blockIdx.x * blockDim.x + threadIdx.x) >> 5;
    const int w = threadIdx.x & 31;
    if (k >= KCODES) return;
    float a = codebook[k * D + 2 * w];
    float b = codebook[k * D + 2 * w + 1];
    __half2 h = __floats2half2_rn(-2.0f * a, -2.0f * b);
    g_cbf[(k >> 3) * 256 + ((k & 7) * 4 + (w & 3)) * 8 + (w >> 2)] =
        *reinterpret_cast<unsigned*>(&h);
    float p = fmaf(a, a, b * b);
#pragma unroll
    for (int o = 16; o > 0; o >>= 1) p += __shfl_xor_sync(0xffffffffu, p, o);
    if (w == 0) g_cnorm[k] = p;
}

// Scores are biased positive (s' = s + BIAS), so raw float bits are an
// order-isomorphic uint key; low 10 bits carry the code index (lowest wins ties).
__device__ __forceinline__ unsigned score_key(float s, int idx) {
    return (__float_as_uint(s) & ~1023u) | (unsigned)idx;   // single LOP3
}
__device__ __forceinline__ void kins2(unsigned kv, unsigned& k0, unsigned& k1) {
    k1 = umin(k1, umax(k0, kv));
    k0 = umin(k0, kv);
}

#define HMMA(c0, c1, c2, c3, a0, a1, a2, a3, b0, b1) \
    asm volatile("mma.sync.aligned.m16n8k16.row.col.f32.f16.f16.f32 " \
        "{%0,%1,%2,%3}, {%4,%5,%6,%7}, {%8,%9}, {%0,%1,%2,%3};" \
        : "+f"(c0), "+f"(c1), "+f"(c2), "+f"(c3) \
        : "r"(a0), "r"(a1), "r"(a2), "r"(a3), "r"(b0), "r"(b1))

// ---- Kernel B: HMMA scoring (2 A-frags/warp) + biased-key top-2 ----
__global__ __launch_bounds__(TPB, 3) void vq_main(const float* __restrict__ inputs,
                                                  const float* __restrict__ codebook,
                                                  float* __restrict__ out) {
    extern __shared__ char smem[];
    unsigned* Aw = reinterpret_cast<unsigned*>(smem + SM_A);
    float*    cn = reinterpret_cast<float*>(smem + SM_CN);

    const int tid  = threadIdx.x;
    const int wid  = tid >> 5;
    const int lane = tid & 31;
    const int g    = lane >> 2;
    const int q    = lane & 3;
    const int tok_base = blockIdx.x * TOKS;

    // Stage A: thread tid stages token tok_base+tid; cn staged with +BIAS.
    {
        const int T = tok_base + tid;
        const int b = T >> 12, hw = T & (HWSZ - 1);
        const float* xin = inputs + (b * D) * HWSZ + hw;
        unsigned* dst = Aw + tid * ASTRIDE_W;
#pragma unroll
        for (int j = 0; j < 32; ++j) {
            __half2 h = __floats2half2_rn(xin[(2 * j) * HWSZ], xin[(2 * j + 1) * HWSZ]);
            dst[j] = *reinterpret_cast<unsigned*>(&h);
        }
        for (int i = tid; i < KCODES; i += TPB) cn[i] = g_cnorm[i] + BIAS;
        const uint4* src = reinterpret_cast<const uint4*>(g_cbf);
        uint4* dstB = reinterpret_cast<uint4*>(smem + SM_B);
        for (int i = tid; i < TILE * 8; i += TPB) dstB[i] = src[i];
    }
    __syncthreads();

    // Two A fragments: tokens wid*32 + f*16 + {g, g+8}.
    unsigned a[2][4][4];
#pragma unroll
    for (int f = 0; f < 2; ++f) {
        const int r0 = (wid * 32 + f * 16 + g) * ASTRIDE_W;
        const int r1 = (wid * 32 + f * 16 + 8 + g) * ASTRIDE_W;
#pragma unroll
        for (int k = 0; k < 4; ++k) {
            a[f][k][0] = Aw[r0 + k * 8 + q];
            a[f][k][1] = Aw[r1 + k * 8 + q];
            a[f][k][2] = Aw[r0 + k * 8 + q + 4];
            a[f][k][3] = Aw[r1 + k * 8 + q + 4];
        }
    }

    unsigned kA0 = 0xffffffffu, kA1 = 0xffffffffu;   // token w*32+g
    unsigned kB0 = 0xffffffffu, kB1 = 0xffffffffu;   // token w*32+8+g
    unsigned kC0 = 0xffffffffu, kC1 = 0xffffffffu;   // token w*32+16+g
    unsigned kD0 = 0xffffffffu, kD1 = 0xffffffffu;   // token w*32+24+g

#pragma unroll 1
    for (int tile = 0; tile < 4; ++tile) {
        if (tile > 0) {
            __syncthreads();
            const uint4* src = reinterpret_cast<const uint4*>(g_cbf) + tile * TILE * 8;
            uint4* dstB = reinterpret_cast<uint4*>(smem + SM_B);
            for (int i = tid; i < TILE * 8; i += TPB) dstB[i] = src[i];
            __syncthreads();
        }
        const int tbase = tile * TILE;
#pragma unroll 2
        for (int ch = 0; ch < TILE / 8; ++ch) {
            const uint4* bp = reinterpret_cast<const uint4*>(smem + SM_B)
                              + ch * 64 + lane * 2;
            uint4 lo = bp[0];
            uint4 hi = bp[1];
            const int g0 = tbase + ch * 8 + 2 * q;
            float2 cnv = *reinterpret_cast<const float2*>(&cn[g0]);
            float c0 = cnv.x, c1 = cnv.y, c2 = cnv.x, c3 = cnv.y;
            float c4 = cnv.x, c5 = cnv.y, c6 = cnv.x, c7 = cnv.y;
            HMMA(c0, c1, c2, c3, a[0][0][0], a[0][0][1], a[0][0][2], a[0][0][3], lo.x, lo.y);
            HMMA(c4, c5, c6, c7, a[1][0][0], a[1][0][1], a[1][0][2], a[1][0][3], lo.x, lo.y);
            HMMA(c0, c1, c2, c3, a[0][1][0], a[0][1][1], a[0][1][2], a[0][1][3], lo.z, lo.w);
            HMMA(c4, c5, c6, c7, a[1][1][0], a[1][1][1], a[1][1][2], a[1][1][3], lo.z, lo.w);
            HMMA(c0, c1, c2, c3, a[0][2][0], a[0][2][1], a[0][2][2], a[0][2][3], hi.x, hi.y);
            HMMA(c4, c5, c6, c7, a[1][2][0], a[1][2][1], a[1][2][2], a[1][2][3], hi.x, hi.y);
            HMMA(c0, c1, c2, c3, a[0][3][0], a[0][3][1], a[0][3][2], a[0][3][3], hi.z, hi.w);
            HMMA(c4, c5, c6, c7, a[1][3][0], a[1][3][1], a[1][3][2], a[1][3][3], hi.z, hi.w);
            kins2(score_key(c0, g0),     kA0, kA1);
            kins2(score_key(c1, g0 + 1), kA0, kA1);
            kins2(score_key(c2, g0),     kB0, kB1);
            kins2(score_key(c3, g0 + 1), kB0, kB1);
            kins2(score_key(c4, g0),     kC0, kC1);
            kins2(score_key(c5, g0 + 1), kC0, kC1);
            kins2(score_key(c6, g0),     kD0, kD1);
            kins2(score_key(c7, g0 + 1), kD0, kD1);
        }
    }

#pragma unroll 1
    for (int row = 0; row < 4; ++row) {
        const int T  = tok_base + wid * 32 + row * 8 + g;
        const int b  = T >> 12, hw = T & (HWSZ - 1);
        unsigned lk0 = (row == 0) ? kA0 : (row == 1) ? kB0 : (row == 2) ? kC0 : kD0;
        unsigned lk1 = (row == 0) ? kA1 : (row == 1) ? kB1 : (row == 2) ? kC1 : kD1;
        unsigned m0 = lk0, m1 = lk1;
#pragma unroll
        for (int d = 1; d <= 2; d <<= 1) {          // quad top-2 merge on keys
            unsigned r0 = __shfl_xor_sync(0xffffffffu, m0, d);
            unsigned r1 = __shfl_xor_sync(0xffffffffu, m1, d);
            kins2(r0, m0, m1);
            m1 = umin(m1, r1);
        }

        unsigned myc = (lk0 & 1023u) | ((lk1 & 1023u) << 16);
        unsigned qb  = lane & ~3u;
        uint4 fc = make_uint4(__shfl_sync(0xffffffffu, myc, qb + 0),
                              __shfl_sync(0xffffffffu, myc, qb + 1),
                              __shfl_sync(0xffffffffu, myc, qb + 2),
                              __shfl_sync(0xffffffffu, myc, qb + 3));

        // Bias cancels in the gap; masked-low-bit keys understate both by <=0.016.
        if (__uint_as_float(m1) - __uint_as_float(m0) < MARGIN) {
            if (q == 0) {
                int wv = atomicAdd(&g_nflag, 1);
                g_ftok[wv]  = T;
                g_fcand[wv] = fc;
            }
        } else {                                        // safe: winner exact
            const int bestk = (int)(m0 & 1023u);
            if (q == 0) atomicAdd(&g_counts[bestk], 1);
            const float* xt = inputs + (b * D) * HWSZ + hw;
            const float* qp = codebook + bestk * D;
            float* op = out + (b * D) * HWSZ + hw;
#pragma unroll
            for (int m = 0; m < 16; ++m) {
                int c = q * 16 + m;
                float xv = __ldg(&xt[c * HWSZ]);
                op[c * HWSZ] = xv + (__ldg(&qp[c]) - xv);
            }
        }
    }
}

__device__ __forceinline__ float wsumf(float p) {
#pragma unroll
    for (int o = 16; o > 0; o >>= 1) p += __shfl_xor_sync(0xffffffffu, p, o);
    return p;
}
__device__ __forceinline__ double wsumd(double p) {
#pragma unroll
    for (int o = 16; o > 0; o >>= 1) p += __shfl_xor_sync(0xffffffffu, p, o);
    return p;
}

// ---- Kernel C: warp-per-token exact rescue + perplexity + replay-state reset ----
__global__ void vq_rescue_perp(const float* __restrict__ inputs,
                               const float* __restrict__ codebook,
                               float* __restrict__ out, int out_size) {
    const int n    = g_nflag;
    const int gw   = (blockIdx.x * blockDim.x + threadIdx.x) >> 5;
    const int lane = threadIdx.x & 31;
    const int nw   = (gridDim.x * blockDim.x) >> 5;

    for (int i = gw; i < n; i += nw) {
        const int T = g_ftok[i];
        const uint4 cw = g_fcand[i];
        int cand[8] = { (int)(cw.x & 0xffff), (int)(cw.x >> 16),
                        (int)(cw.y & 0xffff), (int)(cw.y >> 16),
                        (int)(cw.z & 0xffff), (int)(cw.z >> 16),
                        (int)(cw.w & 0xffff), (int)(cw.w >> 16) };
        const int b = T >> 12, hw = T & (HWSZ - 1);
        const float* xt = inputs + (b * D) * HWSZ + hw;
        float x0 = __ldg(&xt[(2 * lane) * HWSZ]);
        float x1 = __ldg(&xt[(2 * lane + 1) * HWSZ]);

        float e0 = 3.4e38f, e1 = 3.4e38f;
        int   k0 = 0x7fffffff, k1 = 0x7fffffff;
#pragma unroll
        for (int j = 0; j < 8; ++j) {
            int k = cand[j];
            float2 cv = *reinterpret_cast<const float2*>(codebook + k * D + 2 * lane);
            float e = g_cnorm[k] - 2.0f * wsumf(fmaf(x0, cv.x, x1 * cv.y));
            if (e < e0 || (e == e0 && k < k0)) { e1 = e0; k1 = k0; e0 = e; k0 = k; }
            else if (e < e1 || (e == e1 && k < k1)) { e1 = e; k1 = k; }
        }
        int bestk = k0;
        if (e1 - e0 < RESCUE) {                      // fp64 grid rescue (R2-proven)
            double A = wsumd((double)(x0 * x0) + (double)(x1 * x1));
            float A32 = (float)A;
            int klo = min(k0, k1), khi = max(k0, k1);
            float dsc[2];
#pragma unroll
            for (int j = 0; j < 2; ++j) {
                int k = j ? khi : klo;
                float2 cv = *reinterpret_cast<const float2*>(codebook + k * D + 2 * lane);
                double dot = wsumd((double)x0 * (double)cv.x + (double)x1 * (double)cv.y);
                double C   = wsumd((double)(cv.x * cv.x) + (double)(cv.y * cv.y));
                float t1 = (float)dot;
                float t2 = A32 - 2.0f * t1;
                dsc[j] = t2 + (float)C;
            }
            bestk = (dsc[1] < dsc[0]) ? khi : klo;
        }
        if (lane == 0) atomicAdd(&g_counts[bestk], 1);
        float2 qv = *reinterpret_cast<const float2*>(codebook + bestk * D + 2 * lane);
        float* op = out + (b * D) * HWSZ + hw;
        op[(2 * lane) * HWSZ]     = x0 + (qv.x - x0);
        op[(2 * lane + 1) * HWSZ] = x1 + (qv.y - x1);
    }

    // Last CTA: perplexity from final counts, then reset replay state.
    __shared__ int sflag;
    __shared__ float red[8];
    __threadfence();
    __syncthreads();
    if (threadIdx.x == 0) sflag = (atomicAdd(&g_done, 1) == gridDim.x - 1);
    __syncthreads();
    if (!sflag) return;
    __threadfence();

    const int t = threadIdx.x;              // 256 threads, 4 bins each
    float v = 0.f;
#pragma unroll
    for (int j = 0; j < 4; ++j) {
        float e = (float)g_counts[t * 4 + j] * (1.0f / (float)NTOK);
        v += e * logf(e + 1e-10f);
    }
#pragma unroll
    for (int o = 16; o > 0; o >>= 1) v += __shfl_down_sync(0xffffffffu, v, o);
    if ((t & 31) == 0) red[t >> 5] = v;
    __syncthreads();
    if (t == 0) {
        float s = 0.f;
#pragma unroll
        for (int j = 0; j < 8; ++j) s += red[j];
        if (out_size > NTOK * D) out[NTOK * D] = expf(-s);
    }
    __syncthreads();
#pragma unroll
    for (int j = 0; j < 4; ++j) g_counts[t * 4 + j] = 0;
    if (t == 0) { g_nflag = 0; g_done = 0; }
}

extern "C" void kernel_launch(void* const* d_in, const int* in_sizes, int n_in,
                              void* d_out, int out_size) {
    const float* inputs   = (const float*)d_in[0];
    const float* codebook = (const float*)d_in[1];
    float*       out      = (float*)d_out;

    cudaFuncSetAttribute(vq_main, cudaFuncAttributeMaxDynamicSharedMemorySize, SM_TOTAL);

    vq_prep<<<KCODES / 8, TPB>>>(codebook);
    vq_nop<<<1, 1>>>();
    vq_nop<<<1, 1>>>();
    vq_main<<<NTOK / TOKS, TPB, SM_TOTAL>>>(inputs, codebook, out);
    vq_rescue_perp<<<RGRID, TPB>>>(inputs, codebook, out, out_size);
}

// round 12
// speedup vs baseline: 3.1085x; 1.3076x over previous
#include <cuda_runtime.h>
#include <cuda_fp16.h>
#include <math.h>

namespace {
constexpr int KCODES = 1024;
constexpr int D      = 64;
constexpr int HWSZ   = 64 * 64;
constexpr int NTOK   = 32 * HWSZ;        // 131072
constexpr int TPB    = 256;              // 8 warps, 32 tokens/warp -> 256 tokens/CTA
constexpr int TOKS   = 256;
constexpr int TILE   = 256;              // codes per smem B tile (4 tiles)
constexpr float BIAS   = 32.0f;          // |s| <= 2*||x||*||c|| <~ 21 hard -> s+32 > 0
constexpr float MARGIN = 0.045f;         // 0.04 f16-hard + 0.004 key quant @ bias 32
constexpr float RESCUE = 1e-4f;          // fp64 grid-rescue threshold (R2-proven)

constexpr int ASTRIDE_W = 36;            // A row stride in u32 words (144B)
constexpr int SM_A  = 0;                 // 256 * 144B = 36864
constexpr int SM_B  = 36864;             // 256 codes * 128B fragment-packed = 32768
constexpr int SM_CN = 69632;             // 1024 f32 = 4096
constexpr int SM_TOTAL = 73728;          // x3 CTAs = 216 KB
constexpr int RGRID = 256;
}

__device__ float    g_cnorm[KCODES];
__device__ int      g_counts[KCODES];
__device__ unsigned g_cbf[KCODES * 32];    // f16x2 of (-2c), MMA-fragment-packed
__device__ int      g_nflag;
__device__ int      g_done;
__device__ int      g_ftok[NTOK];
__device__ uint4    g_fcand[NTOK];         // 8 candidate ids: 4 x (u16|u16)

__global__ void vq_nop() {}

// ---- Kernel A: warp-per-code prep: norms + fragment-packed f16(-2c) ----
__global__ void vq_prep(const float* __restrict__ codebook) {
    const int k = (blockIdx.x * blockDim.x + threadIdx.x) >> 5;
    const int w = threadIdx.x & 31;
    if (k >= KCODES) return;
    float a = codebook[k * D + 2 * w];
    float b = codebook[k * D + 2 * w + 1];
    __half2 h = __floats2half2_rn(-2.0f * a, -2.0f * b);
    g_cbf[(k >> 3) * 256 + ((k & 7) * 4 + (w & 3)) * 8 + (w >> 2)] =
        *reinterpret_cast<unsigned*>(&h);
    float p = fmaf(a, a, b * b);
#pragma unroll
    for (int o = 16; o > 0; o >>= 1) p += __shfl_xor_sync(0xffffffffu, p, o);
    if (w == 0) g_cnorm[k] = p;
}

// Biased-positive scores: raw float bits are an order-isomorphic uint key;
// low 10 bits carry the code index so umin() keeps the lowest index on ties.
__device__ __forceinline__ unsigned score_key(float s, int idx) {
    return (__float_as_uint(s) & ~1023u) | (unsigned)idx;   // single LOP3
}
__device__ __forceinline__ void kins2(unsigned kv, unsigned& k0, unsigned& k1) {
    k1 = umin(k1, umax(k0, kv));
    k0 = umin(k0, kv);
}

#define HMMA(c0, c1, c2, c3, a0, a1, a2, a3, b0, b1) \
    asm volatile("mma.sync.aligned.m16n8k16.row.col.f32.f16.f16.f32 " \
        "{%0,%1,%2,%3}, {%4,%5,%6,%7}, {%8,%9}, {%0,%1,%2,%3};" \
        : "+f"(c0), "+f"(c1), "+f"(c2), "+f"(c3) \
        : "r"(a0), "r"(a1), "r"(a2), "r"(a3), "r"(b0), "r"(b1))

// ---- Kernel B: HMMA scoring (2 A-frags/warp) + biased-key top-2 ----
__global__ __launch_bounds__(TPB, 3) void vq_main(const float* __restrict__ inputs,
                                                  const float* __restrict__ codebook,
                                                  float* __restrict__ out) {
    extern __shared__ char smem[];
    unsigned* Aw = reinterpret_cast<unsigned*>(smem + SM_A);
    float*    cn = reinterpret_cast<float*>(smem + SM_CN);

    const int tid  = threadIdx.x;
    const int wid  = tid >> 5;
    const int lane = tid & 31;
    const int g    = lane >> 2;
    const int q    = lane & 3;
    const int tok_base = blockIdx.x * TOKS;

    {
        const int T = tok_base + tid;
        const int b = T >> 12, hw = T & (HWSZ - 1);
        const float* xin = inputs + (b * D) * HWSZ + hw;
        unsigned* dst = Aw + tid * ASTRIDE_W;
#pragma unroll
        for (int j = 0; j < 32; ++j) {
            __half2 h = __floats2half2_rn(xin[(2 * j) * HWSZ], xin[(2 * j + 1) * HWSZ]);
            dst[j] = *reinterpret_cast<unsigned*>(&h);
        }
        for (int i = tid; i < KCODES; i += TPB) cn[i] = g_cnorm[i] + BIAS;
        const uint4* src = reinterpret_cast<const uint4*>(g_cbf);
        uint4* dstB = reinterpret_cast<uint4*>(smem + SM_B);
        for (int i = tid; i < TILE * 8; i += TPB) dstB[i] = src[i];
    }
    __syncthreads();

    unsigned a[2][4][4];
#pragma unroll
    for (int f = 0; f < 2; ++f) {
        const int r0 = (wid * 32 + f * 16 + g) * ASTRIDE_W;
        const int r1 = (wid * 32 + f * 16 + 8 + g) * ASTRIDE_W;
#pragma unroll
        for (int k = 0; k < 4; ++k) {
            a[f][k][0] = Aw[r0 + k * 8 + q];
            a[f][k][1] = Aw[r1 + k * 8 + q];
            a[f][k][2] = Aw[r0 + k * 8 + q + 4];
            a[f][k][3] = Aw[r1 + k * 8 + q + 4];
        }
    }

    unsigned kA0 = 0xffffffffu, kA1 = 0xffffffffu;
    unsigned kB0 = 0xffffffffu, kB1 = 0xffffffffu;
    unsigned kC0 = 0xffffffffu, kC1 = 0xffffffffu;
    unsigned kD0 = 0xffffffffu, kD1 = 0xffffffffu;

#pragma unroll 1
    for (int tile = 0; tile < 4; ++tile) {
        if (tile > 0) {
            __syncthreads();
            const uint4* src = reinterpret_cast<const uint4*>(g_cbf) + tile * TILE * 8;
            uint4* dstB = reinterpret_cast<uint4*>(smem + SM_B);
            for (int i = tid; i < TILE * 8; i += TPB) dstB[i] = src[i];
            __syncthreads();
        }
        const int tbase = tile * TILE;
#pragma unroll 2
        for (int ch = 0; ch < TILE / 8; ++ch) {
            const uint4* bp = reinterpret_cast<const uint4*>(smem + SM_B)
                              + ch * 64 + lane * 2;
            uint4 lo = bp[0];
            uint4 hi = bp[1];
            const int g0 = tbase + ch * 8 + 2 * q;
            float2 cnv = *reinterpret_cast<const float2*>(&cn[g0]);
            float c0 = cnv.x, c1 = cnv.y, c2 = cnv.x, c3 = cnv.y;
            float c4 = cnv.x, c5 = cnv.y, c6 = cnv.x, c7 = cnv.y;
            HMMA(c0, c1, c2, c3, a[0][0][0], a[0][0][1], a[0][0][2], a[0][0][3], lo.x, lo.y);
            HMMA(c4, c5, c6, c7, a[1][0][0], a[1][0][1], a[1][0][2], a[1][0][3], lo.x, lo.y);
            HMMA(c0, c1, c2, c3, a[0][1][0], a[0][1][1], a[0][1][2], a[0][1][3], lo.z, lo.w);
            HMMA(c4, c5, c6, c7, a[1][1][0], a[1][1][1], a[1][1][2], a[1][1][3], lo.z, lo.w);
            HMMA(c0, c1, c2, c3, a[0][2][0], a[0][2][1], a[0][2][2], a[0][2][3], hi.x, hi.y);
            HMMA(c4, c5, c6, c7, a[1][2][0], a[1][2][1], a[1][2][2], a[1][2][3], hi.x, hi.y);
            HMMA(c0, c1, c2, c3, a[0][3][0], a[0][3][1], a[0][3][2], a[0][3][3], hi.z, hi.w);
            HMMA(c4, c5, c6, c7, a[1][3][0], a[1][3][1], a[1][3][2], a[1][3][3], hi.z, hi.w);
            kins2(score_key(c0, g0),     kA0, kA1);
            kins2(score_key(c1, g0 + 1), kA0, kA1);
            kins2(score_key(c2, g0),     kB0, kB1);
            kins2(score_key(c3, g0 + 1), kB0, kB1);
            kins2(score_key(c4, g0),     kC0, kC1);
            kins2(score_key(c5, g0 + 1), kC0, kC1);
            kins2(score_key(c6, g0),     kD0, kD1);
            kins2(score_key(c7, g0 + 1), kD0, kD1);
        }
    }

#pragma unroll 1
    for (int row = 0; row < 4; ++row) {
        const int T  = tok_base + wid * 32 + row * 8 + g;
        const int b  = T >> 12, hw = T & (HWSZ - 1);
        unsigned lk0 = (row == 0) ? kA0 : (row == 1) ? kB0 : (row == 2) ? kC0 : kD0;
        unsigned lk1 = (row == 0) ? kA1 : (row == 1) ? kB1 : (row == 2) ? kC1 : kD1;
        unsigned m0 = lk0, m1 = lk1;
#pragma unroll
        for (int d = 1; d <= 2; d <<= 1) {
            unsigned r0 = __shfl_xor_sync(0xffffffffu, m0, d);
            unsigned r1 = __shfl_xor_sync(0xffffffffu, m1, d);
            kins2(r0, m0, m1);
            m1 = umin(m1, r1);
        }

        unsigned myc = (lk0 & 1023u) | ((lk1 & 1023u) << 16);
        unsigned qb  = lane & ~3u;
        uint4 fc = make_uint4(__shfl_sync(0xffffffffu, myc, qb + 0),
                              __shfl_sync(0xffffffffu, myc, qb + 1),
                              __shfl_sync(0xffffffffu, myc, qb + 2),
                              __shfl_sync(0xffffffffu, myc, qb + 3));

        if (__uint_as_float(m1) - __uint_as_float(m0) < MARGIN) {
            if (q == 0) {
                int wv = atomicAdd(&g_nflag, 1);
                g_ftok[wv]  = T;
                g_fcand[wv] = fc;
            }
        } else {
            const int bestk = (int)(m0 & 1023u);
            if (q == 0) atomicAdd(&g_counts[bestk], 1);
            const float* xt = inputs + (b * D) * HWSZ + hw;
            const float* qp = codebook + bestk * D;
            float* op = out + (b * D) * HWSZ + hw;
#pragma unroll
            for (int m = 0; m < 16; ++m) {
                int c = q * 16 + m;
                float xv = __ldg(&xt[c * HWSZ]);
                op[c * HWSZ] = xv + (__ldg(&qp[c]) - xv);
            }
        }
    }
}

__device__ __forceinline__ double wsumd(double p) {
#pragma unroll
    for (int o = 16; o > 0; o >>= 1) p += __shfl_xor_sync(0xffffffffu, p, o);
    return p;
}
__device__ __forceinline__ void ins2f(float s, int i, float& e0, int& k0,
                                      float& e1, int& k1) {
    if (s < e0 || (s == e0 && i < k0)) { e1 = e0; k1 = k0; e0 = s; k0 = i; }
    else if (s < e1 || (s == e1 && i < k1)) { e1 = s; k1 = i; }
}

// ---- Kernel C: quad-parallel exact rescue + perplexity + replay-state reset ----
// Warp per token; lane = (candidate j = lane/4, quarter qq = lane%4).
__global__ void vq_rescue_perp(const float* __restrict__ inputs,
                               const float* __restrict__ codebook,
                               float* __restrict__ out, int out_size) {
    const int n    = g_nflag;
    const int gw   = (blockIdx.x * blockDim.x + threadIdx.x) >> 5;
    const int lane = threadIdx.x & 31;
    const int nw   = (gridDim.x * blockDim.x) >> 5;
    const int j    = lane >> 2;          // candidate slot 0..7
    const int qq   = lane & 3;           // 16-dim quarter

    for (int i = gw; i < n; i += nw) {
        const int T = g_ftok[i];
        const uint4 cw = g_fcand[i];
        const unsigned cand2[4] = { cw.x, cw.y, cw.z, cw.w };
        const int k = (int)((cand2[j >> 1] >> ((j & 1) * 16)) & 0xffffu);
        const int b = T >> 12, hw = T & (HWSZ - 1);
        const float* xt = inputs + (b * D) * HWSZ + hw;

        // 16-dim partial dot: exact fp32 4-way-split form (matches R9-proven scorer
        // when combined with +-reduction order below).
        float xs[16];
#pragma unroll
        for (int m = 0; m < 16; ++m) xs[m] = __ldg(&xt[(qq * 16 + m) * HWSZ]);
        const float4* cp = reinterpret_cast<const float4*>(codebook + k * D + qq * 16);
        float d0 = 0.f, d1 = 0.f, d2 = 0.f, d3 = 0.f;
#pragma unroll
        for (int w = 0; w < 4; ++w) {
            float4 cv = __ldg(&cp[w]);
            d0 = fmaf(xs[4 * w + 0], cv.x, d0);
            d1 = fmaf(xs[4 * w + 1], cv.y, d1);
            d2 = fmaf(xs[4 * w + 2], cv.z, d2);
            d3 = fmaf(xs[4 * w + 3], cv.w, d3);
        }
        float part = (d0 + d1) + (d2 + d3);
        part += __shfl_xor_sync(0xffffffffu, part, 1);
        part += __shfl_xor_sync(0xffffffffu, part, 2);
        float e = g_cnorm[k] - 2.0f * part;      // exact fp32 score, all quad lanes

        // Merge top-2 across the 8 candidate groups (xor butterfly d=4,8,16).
        float e0 = e, e1 = 3.4e38f;
        int   k0 = k, k1 = 0x7fffffff;
#pragma unroll
        for (int d = 4; d <= 16; d <<= 1) {
            float re0 = __shfl_xor_sync(0xffffffffu, e0, d);
            float re1 = __shfl_xor_sync(0xffffffffu, e1, d);
            int   rk0 = __shfl_xor_sync(0xffffffffu, k0, d);
            int   rk1 = __shfl_xor_sync(0xffffffffu, k1, d);
            ins2f(re0, rk0, e0, k0, e1, k1);
            ins2f(re1, rk1, e0, k0, e1, k1);
        }

        int bestk = k0;
        float x0 = __ldg(&xt[(2 * lane) * HWSZ]);
        float x1 = __ldg(&xt[(2 * lane + 1) * HWSZ]);
        if (e1 - e0 < RESCUE) {                  // fp64 grid rescue (R2-proven)
            double A = wsumd((double)(x0 * x0) + (double)(x1 * x1));
            float A32 = (float)A;
            int klo = min(k0, k1), khi = max(k0, k1);
            float dsc[2];
#pragma unroll
            for (int jj = 0; jj < 2; ++jj) {
                int kk = jj ? khi : klo;
                float2 cv = *reinterpret_cast<const float2*>(codebook + kk * D + 2 * lane);
                double dot = wsumd((double)x0 * (double)cv.x + (double)x1 * (double)cv.y);
                double C   = wsumd((double)(cv.x * cv.x) + (double)(cv.y * cv.y));
                float t1 = (float)dot;
                float t2 = A32 - 2.0f * t1;
                dsc[jj] = t2 + (float)C;
            }
            bestk = (dsc[1] < dsc[0]) ? khi : klo;
        }
        if (lane == 0) atomicAdd(&g_counts[bestk], 1);
        float2 qv = *reinterpret_cast<const float2*>(codebook + bestk * D + 2 * lane);
        float* op = out + (b * D) * HWSZ + hw;
        op[(2 * lane) * HWSZ]     = x0 + (qv.x - x0);
        op[(2 * lane + 1) * HWSZ] = x1 + (qv.y - x1);
    }

    // Last CTA: perplexity from final counts, then reset replay state.
    __shared__ int sflag;
    __shared__ float red[8];
    __threadfence();
    __syncthreads();
    if (threadIdx.x == 0) sflag = (atomicAdd(&g_done, 1) == gridDim.x - 1);
    __syncthreads();
    if (!sflag) return;
    __threadfence();

    const int t = threadIdx.x;
    float v = 0.f;
#pragma unroll
    for (int jj = 0; jj < 4; ++jj) {
        float e = (float)g_counts[t * 4 + jj] * (1.0f / (float)NTOK);
        v += e * logf(e + 1e-10f);
    }
#pragma unroll
    for (int o = 16; o > 0; o >>= 1) v += __shfl_down_sync(0xffffffffu, v, o);
    if ((t & 31) == 0) red[t >> 5] = v;
    __syncthreads();
    if (t == 0) {
        float s = 0.f;
#pragma unroll
        for (int jj = 0; jj < 8; ++jj) s += red[jj];
        if (out_size > NTOK * D) out[NTOK * D] = expf(-s);
    }
    __syncthreads();
#pragma unroll
    for (int jj = 0; jj < 4; ++jj) g_counts[t * 4 + jj] = 0;
    if (t == 0) { g_nflag = 0; g_done = 0; }
}

extern "C" void kernel_launch(void* const* d_in, const int* in_sizes, int n_in,
                              void* d_out, int out_size) {
    const float* inputs   = (const float*)d_in[0];
    const float* codebook = (const float*)d_in[1];
    float*       out      = (float*)d_out;

    cudaFuncSetAttribute(vq_main, cudaFuncAttributeMaxDynamicSharedMemorySize, SM_TOTAL);

    vq_prep<<<KCODES / 8, TPB>>>(codebook);
    vq_nop<<<1, 1>>>();
    vq_nop<<<1, 1>>>();
    vq_main<<<NTOK / TOKS, TPB, SM_TOTAL>>>(inputs, codebook, out);
    vq_rescue_perp<<<RGRID, TPB>>>(inputs, codebook, out, out_size);
}